// round 6
// baseline (speedup 1.0000x reference)
#include <cuda_runtime.h>
#include <cuda_bf16.h>
#include <cstdint>

// Problem constants
#define B_SZ 4096
#define MAX_LEN 128
#define EMB_D 300
#define REP_D 600
#define HID 1000
#define NCLS 5

#define KPAD 640      // 600 padded to 10 chunks of 64 (int8)
#define NPAD 1024     // 1000 padded to 8 tiles of 128
#define BK 64
#define NCHUNK (KPAD / BK)   // 10

// Fixed-point: v ~= s * (hi*256 + lo), q = round(v/s) clamped to +-32639
#define BOUND_A 0.75f
#define BOUND_B 0.25f
#define QA (32768.0f / BOUND_A)
#define QB (32768.0f / BOUND_B)
#define OUT_SCALE ((BOUND_A * BOUND_B) / (32768.0f * 32768.0f))

// ---------------------------------------------------------------------------
// Scratch (no cudaMalloc allowed)
// ---------------------------------------------------------------------------
__device__ __align__(128) int8_t g_a_hi[B_SZ * KPAD];   // rep hi  [4096,640]
__device__ __align__(128) int8_t g_a_lo[B_SZ * KPAD];   // rep lo
__device__ __align__(128) int8_t g_b_hi[NPAD * KPAD];   // W1^T hi [1024,640]
__device__ __align__(128) int8_t g_b_lo[NPAD * KPAD];   // W1^T lo

// ---------------------------------------------------------------------------
// PTX helpers (family-portable: ldmatrix / mma.sync s8 / cp.async)
// ---------------------------------------------------------------------------
__device__ __forceinline__ uint32_t smem_u32(const void* p) {
    uint32_t a;
    asm("{ .reg .u64 t; cvta.to.shared.u64 t, %1; cvt.u32.u64 %0, t; }"
        : "=r"(a) : "l"(p));
    return a;
}

__device__ __forceinline__ void cp_async16(uint32_t smem_dst, const void* gmem_src) {
    asm volatile("cp.async.ca.shared.global [%0], [%1], 16;"
                 :: "r"(smem_dst), "l"(gmem_src));
}
#define CP_COMMIT() asm volatile("cp.async.commit_group;" ::: "memory")
#define CP_WAIT(n)  asm volatile("cp.async.wait_group %0;" :: "n"(n) : "memory")

__device__ __forceinline__ void ldsm4(uint32_t* r, uint32_t addr) {
    asm volatile("ldmatrix.sync.aligned.m8n8.x4.shared.b16 {%0,%1,%2,%3}, [%4];"
                 : "=r"(r[0]), "=r"(r[1]), "=r"(r[2]), "=r"(r[3]) : "r"(addr));
}

__device__ __forceinline__ void imma16832(int* c, const uint32_t* a,
                                          uint32_t b0, uint32_t b1) {
    asm volatile(
        "mma.sync.aligned.m16n8k32.row.col.s32.s8.s8.s32 "
        "{%0,%1,%2,%3}, {%4,%5,%6,%7}, {%8,%9}, {%0,%1,%2,%3};"
        : "+r"(c[0]), "+r"(c[1]), "+r"(c[2]), "+r"(c[3])
        : "r"(a[0]), "r"(a[1]), "r"(a[2]), "r"(a[3]), "r"(b0), "r"(b1));
}

// q in [-32639, 32639] -> (hi, lo), q = hi*256 + lo, both in [-128,127]
__device__ __forceinline__ void fsplit(float v, float qs, int8_t& hi, int8_t& lo) {
    int q = __float2int_rn(v * qs);
    q = max(-32639, min(32639, q));
    const int h = (q + 128) >> 8;
    hi = (int8_t)h;
    lo = (int8_t)(q - (h << 8));
}

// ---------------------------------------------------------------------------
// Pooling (float4) + self dtype-detect + out init. int8 hi/lo outputs.
// One block (80 threads) per batch row; tx<75 owns one float4 of dims.
// lengths in [1,127]: raw word[1]==0 <=> int64 layout.
// ---------------------------------------------------------------------------
__global__ void __launch_bounds__(80) pool_kernel(
    const void* __restrict__ xv, const void* __restrict__ lenv,
    const float* __restrict__ emb, const float* __restrict__ b2,
    float* __restrict__ out)
{
    __shared__ int idx_s[MAX_LEN];
    const int b = blockIdx.x;
    const int tid = threadIdx.x;

    const int is64 = (((const unsigned*)lenv)[1] == 0u);

    int len;
    if (is64) {
        len = (int)((const long long*)lenv)[b];
        for (int i = tid; i < len; i += 80)
            idx_s[i] = (int)((const long long*)xv)[(long)b * MAX_LEN + i];
    } else {
        len = ((const int*)lenv)[b];
        for (int i = tid; i < len; i += 80)
            idx_s[i] = ((const int*)xv)[(long)b * MAX_LEN + i];
    }
    __syncthreads();

    const long rowb = (long)b * KPAD;

    if (tid < NCLS)
        out[(long)b * NCLS + tid] = __ldg(&b2[tid]);

    if (tid >= 75) {
        // zero K padding cols 600..639 (5 threads x 8 bytes)
        const int d0 = REP_D + (tid - 75) * 8;
        *(uint2*)&g_a_hi[rowb + d0] = make_uint2(0u, 0u);
        *(uint2*)&g_a_lo[rowb + d0] = make_uint2(0u, 0u);
        return;
    }

    const float4* base = (const float4*)emb;   // emb rows: 75 float4 each
    float4 s  = make_float4(0.f, 0.f, 0.f, 0.f);
    float4 mx = make_float4(-3.402823466e38f, -3.402823466e38f,
                            -3.402823466e38f, -3.402823466e38f);
#pragma unroll 4
    for (int t = 0; t < len; ++t) {
        const float4 v = __ldg(&base[(long)idx_s[t] * 75 + tid]);
        s.x += v.x; s.y += v.y; s.z += v.z; s.w += v.w;
        mx.x = fmaxf(mx.x, v.x); mx.y = fmaxf(mx.y, v.y);
        mx.z = fmaxf(mx.z, v.z); mx.w = fmaxf(mx.w, v.w);
    }
    const float inv = 1.0f / (float)len;
    const int d = 4 * tid;

    {
        char4 h, l;
        fsplit(s.x * inv, QA, (int8_t&)h.x, (int8_t&)l.x);
        fsplit(s.y * inv, QA, (int8_t&)h.y, (int8_t&)l.y);
        fsplit(s.z * inv, QA, (int8_t&)h.z, (int8_t&)l.z);
        fsplit(s.w * inv, QA, (int8_t&)h.w, (int8_t&)l.w);
        *(char4*)&g_a_hi[rowb + d] = h;
        *(char4*)&g_a_lo[rowb + d] = l;
    }
    {
        char4 h, l;
        fsplit(mx.x, QA, (int8_t&)h.x, (int8_t&)l.x);
        fsplit(mx.y, QA, (int8_t&)h.y, (int8_t&)l.y);
        fsplit(mx.z, QA, (int8_t&)h.z, (int8_t&)l.z);
        fsplit(mx.w, QA, (int8_t&)h.w, (int8_t&)l.w);
        *(char4*)&g_a_hi[rowb + EMB_D + d] = h;
        *(char4*)&g_a_lo[rowb + EMB_D + d] = l;
    }
}

// ---------------------------------------------------------------------------
// W1 [600,1000] fp32 -> transposed padded int8 hi/lo [1024,640]
// smem 32x32 tile transpose: coalesced reads; writes are 32B/warp-segment.
// ---------------------------------------------------------------------------
__global__ void __launch_bounds__(256) convert_w1_kernel(const float* __restrict__ W1) {
    __shared__ float tile[32][33];
    const int k0 = blockIdx.x * 32;
    const int n0 = blockIdx.y * 32;
    const int tx = threadIdx.x;   // 0..31
    const int ty = threadIdx.y;   // 0..7

#pragma unroll
    for (int i = 0; i < 4; ++i) {
        const int k = k0 + ty + i * 8;
        const int n = n0 + tx;
        tile[ty + i * 8][tx] = (k < REP_D && n < HID) ? __ldg(&W1[(long)k * HID + n]) : 0.0f;
    }
    __syncthreads();

#pragma unroll
    for (int i = 0; i < 4; ++i) {
        const int n = n0 + ty + i * 8;
        const int k = k0 + tx;
        int8_t hi, lo;
        fsplit(tile[tx][ty + i * 8], QB, hi, lo);
        g_b_hi[(long)n * KPAD + k] = hi;
        g_b_lo[(long)n * KPAD + k] = lo;
    }
}

// ---------------------------------------------------------------------------
// Fused GEMM1 (int8x3 exact fixed-point via mma.m16n8k32.s8) + bias/ReLU + GEMM2.
// CTA tile M=128,N=128; 16 warps (4m x 4n), warp tile 32x32.
// acc = 65536*HH + 256*(HL+LH); HL+LH share one s32 accumulator set.
// BK=64 int8 per chunk, double-buffered, single syncthreads per chunk.
// ---------------------------------------------------------------------------
#define LDSI 80                       // bytes per smem row (64 + 16 pad)
#define TILE_B (128 * LDSI)           // 10240
#define STAGE_B (4 * TILE_B)          // 40960: [A_HI, A_LO, B_HI, B_LO]
#define SMEM_BYTES (2 * STAGE_B)      // 81920

__device__ __forceinline__ void fill_stage(
    uint32_t sbase, int tid, int kc,
    const int8_t* gah, const int8_t* gal,
    const int8_t* gbh, const int8_t* gbl)
{
    const int row = tid >> 2, seg = tid & 3;
    const uint32_t so = (uint32_t)(row * LDSI + seg * 16);
    const long go = (long)row * KPAD + kc + seg * 16;
    cp_async16(sbase + 0 * TILE_B + so, gah + go);
    cp_async16(sbase + 1 * TILE_B + so, gal + go);
    cp_async16(sbase + 2 * TILE_B + so, gbh + go);
    cp_async16(sbase + 3 * TILE_B + so, gbl + go);
}

__global__ void __launch_bounds__(512, 1) mma_kernel(
    const float* __restrict__ b1, const float* __restrict__ W2,
    float* __restrict__ out)
{
    extern __shared__ __align__(128) char smem[];
    const uint32_t sb = smem_u32(smem);
    const int tid  = threadIdx.x;
    const int wid  = tid >> 5;
    const int lane = tid & 31;
    const int warp_m = wid >> 2;      // 0..3
    const int warp_n = wid & 3;       // 0..3
    const int n0 = blockIdx.x * 128;
    const int m0 = blockIdx.y * 128;

    const int8_t* gah = g_a_hi + (long)m0 * KPAD;
    const int8_t* gal = g_a_lo + (long)m0 * KPAD;
    const int8_t* gbh = g_b_hi + (long)n0 * KPAD;
    const int8_t* gbl = g_b_lo + (long)n0 * KPAD;

    int accH[2][4][4];   // hi*hi
    int accX[2][4][4];   // hi*lo + lo*hi
#pragma unroll
    for (int a = 0; a < 2; ++a)
#pragma unroll
        for (int b = 0; b < 4; ++b)
#pragma unroll
            for (int d = 0; d < 4; ++d) { accH[a][b][d] = 0; accX[a][b][d] = 0; }

    // ldmatrix per-lane address components (bytes)
    const int a_row16 = (lane & 7) + ((lane >> 3) & 1) * 8;
    const int a_koff  = (lane >> 4) * 16;
    const int b_n16   = (lane & 7) + (lane >> 4) * 8;
    const int b_koff  = ((lane >> 3) & 1) * 16;

    fill_stage(sb, tid, 0, gah, gal, gbh, gbl);
    CP_COMMIT();

    for (int c = 0; c < NCHUNK; ++c) {
        const uint32_t cur = sb + (uint32_t)(c & 1) * STAGE_B;

        CP_WAIT(0);
        __syncthreads();
        if (c + 1 < NCHUNK) {
            fill_stage(sb + (uint32_t)((c + 1) & 1) * STAGE_B, tid,
                       (c + 1) * BK, gah, gal, gbh, gbl);
            CP_COMMIT();
        }

#pragma unroll
        for (int ks = 0; ks < 2; ++ks) {            // two k32 steps per chunk
            const int kb = ks * 32;
            uint32_t ah[2][4], al[2][4];
#pragma unroll
            for (int mf = 0; mf < 2; ++mf) {
                const uint32_t aoff =
                    (uint32_t)((warp_m * 32 + mf * 16 + a_row16) * LDSI + kb + a_koff);
                ldsm4(ah[mf], cur + 0 * TILE_B + aoff);
                ldsm4(al[mf], cur + 1 * TILE_B + aoff);
            }
#pragma unroll
            for (int nf2 = 0; nf2 < 2; ++nf2) {
                const uint32_t boff =
                    (uint32_t)((warp_n * 32 + nf2 * 16 + b_n16) * LDSI + kb + b_koff);
                uint32_t rh[4], rl[4];
                ldsm4(rh, cur + 2 * TILE_B + boff);
                ldsm4(rl, cur + 3 * TILE_B + boff);
#pragma unroll
                for (int mf = 0; mf < 2; ++mf) {
                    imma16832(accH[mf][nf2 * 2 + 0], ah[mf], rh[0], rh[1]);
                    imma16832(accH[mf][nf2 * 2 + 1], ah[mf], rh[2], rh[3]);
                    imma16832(accX[mf][nf2 * 2 + 0], ah[mf], rl[0], rl[1]);
                    imma16832(accX[mf][nf2 * 2 + 1], ah[mf], rl[2], rl[3]);
                    imma16832(accX[mf][nf2 * 2 + 0], al[mf], rh[0], rh[1]);
                    imma16832(accX[mf][nf2 * 2 + 1], al[mf], rh[2], rh[3]);
                }
            }
        }
    }
    __syncthreads();

    // --- Fused epilogue: dequant + bias + relu + W2 dot + atomic accumulate ---
    float* w2s = (float*)(smem);            // 128*5 floats
    float* b1s = (float*)(smem + 2560);     // 128 floats
    for (int i = tid; i < 128 * NCLS; i += 512) {
        const int n = n0 + i / NCLS;
        w2s[i] = (n < HID) ? __ldg(&W2[(long)n * NCLS + (i % NCLS)]) : 0.0f;
    }
    if (tid < 128) {
        const int n = n0 + tid;
        b1s[tid] = (n < HID) ? __ldg(&b1[n]) : 0.0f;
    }
    __syncthreads();

#pragma unroll
    for (int mf = 0; mf < 2; ++mf) {
#pragma unroll
        for (int h = 0; h < 2; ++h) {
            const int m = m0 + warp_m * 32 + mf * 16 + (lane >> 2) + 8 * h;
            float p0 = 0.f, p1 = 0.f, p2 = 0.f, p3 = 0.f, p4 = 0.f;
#pragma unroll
            for (int nf = 0; nf < 4; ++nf) {
                const int nl = warp_n * 32 + nf * 8 + 2 * (lane & 3);
                const float r0 = 65536.0f * (float)accH[mf][nf][2 * h + 0]
                               +   256.0f * (float)accX[mf][nf][2 * h + 0];
                const float r1 = 65536.0f * (float)accH[mf][nf][2 * h + 1]
                               +   256.0f * (float)accX[mf][nf][2 * h + 1];
                const float v0 = fmaxf(r0 * OUT_SCALE + b1s[nl], 0.0f);
                const float v1 = fmaxf(r1 * OUT_SCALE + b1s[nl + 1], 0.0f);
                p0 += v0 * w2s[nl * NCLS + 0] + v1 * w2s[(nl + 1) * NCLS + 0];
                p1 += v0 * w2s[nl * NCLS + 1] + v1 * w2s[(nl + 1) * NCLS + 1];
                p2 += v0 * w2s[nl * NCLS + 2] + v1 * w2s[(nl + 1) * NCLS + 2];
                p3 += v0 * w2s[nl * NCLS + 3] + v1 * w2s[(nl + 1) * NCLS + 3];
                p4 += v0 * w2s[nl * NCLS + 4] + v1 * w2s[(nl + 1) * NCLS + 4];
            }
#pragma unroll
            for (int off = 1; off <= 2; off <<= 1) {
                p0 += __shfl_xor_sync(0xffffffffu, p0, off);
                p1 += __shfl_xor_sync(0xffffffffu, p1, off);
                p2 += __shfl_xor_sync(0xffffffffu, p2, off);
                p3 += __shfl_xor_sync(0xffffffffu, p3, off);
                p4 += __shfl_xor_sync(0xffffffffu, p4, off);
            }
            if ((lane & 3) == 0) {
                atomicAdd(&out[(long)m * NCLS + 0], p0);
                atomicAdd(&out[(long)m * NCLS + 1], p1);
                atomicAdd(&out[(long)m * NCLS + 2], p2);
                atomicAdd(&out[(long)m * NCLS + 3], p3);
                atomicAdd(&out[(long)m * NCLS + 4], p4);
            }
        }
    }
}

// ---------------------------------------------------------------------------
extern "C" void kernel_launch(void* const* d_in, const int* in_sizes, int n_in,
                              void* d_out, int out_size)
{
    const void*  x       = d_in[0];
    const void*  lengths = d_in[1];
    const float* emb     = (const float*)d_in[2];
    const float* W1      = (const float*)d_in[3];
    const float* b1      = (const float*)d_in[4];
    const float* W2      = (const float*)d_in[5];
    const float* b2      = (const float*)d_in[6];
    float* out = (float*)d_out;

    cudaFuncSetAttribute(mma_kernel, cudaFuncAttributeMaxDynamicSharedMemorySize,
                         (int)SMEM_BYTES);

    pool_kernel<<<B_SZ, 80>>>(x, lengths, emb, b2, out);

    dim3 cb(32, 8);
    dim3 cg(KPAD / 32, NPAD / 32);   // (20, 32)
    convert_w1_kernel<<<cg, cb>>>(W1);

    dim3 g(NPAD / 128, B_SZ / 128);  // (8, 32)
    mma_kernel<<<g, 512, SMEM_BYTES>>>(b1, W2, out);
}

// round 7
// speedup vs baseline: 2.3901x; 2.3901x over previous
#include <cuda_runtime.h>
#include <cuda_fp16.h>
#include <cstdint>

// Problem constants
#define B_SZ 4096
#define MAX_LEN 128
#define EMB_D 300
#define REP_D 600
#define HID 1000
#define NCLS 5

#define KPAD 640      // 600 padded to 20 chunks of 32
#define NPAD 1024     // 1000 padded to 8 tiles of 128
#define BK 32
#define NCHUNK (KPAD / BK)   // 20

// ---------------------------------------------------------------------------
// Scratch (no cudaMalloc allowed)
// ---------------------------------------------------------------------------
__device__ __align__(128) __half g_a_hi[B_SZ * KPAD];   // rep hi  [4096,640]
__device__ __align__(128) __half g_a_lo[B_SZ * KPAD];   // rep lo (A residual)
__device__ __align__(128) __half g_b_hi[NPAD * KPAD];   // W1^T   [1024,640]

// ---------------------------------------------------------------------------
// PTX helpers (family-portable: ldmatrix / mma.sync / cp.async)
// ---------------------------------------------------------------------------
__device__ __forceinline__ uint32_t smem_u32(const void* p) {
    uint32_t a;
    asm("{ .reg .u64 t; cvta.to.shared.u64 t, %1; cvt.u32.u64 %0, t; }"
        : "=r"(a) : "l"(p));
    return a;
}

__device__ __forceinline__ void cp_async16(uint32_t smem_dst, const void* gmem_src) {
    asm volatile("cp.async.ca.shared.global [%0], [%1], 16;"
                 :: "r"(smem_dst), "l"(gmem_src));
}
#define CP_COMMIT() asm volatile("cp.async.commit_group;" ::: "memory")
#define CP_WAIT(n)  asm volatile("cp.async.wait_group %0;" :: "n"(n) : "memory")

__device__ __forceinline__ void ldsm4(uint32_t* r, uint32_t addr) {
    asm volatile("ldmatrix.sync.aligned.m8n8.x4.shared.b16 {%0,%1,%2,%3}, [%4];"
                 : "=r"(r[0]), "=r"(r[1]), "=r"(r[2]), "=r"(r[3]) : "r"(addr));
}

__device__ __forceinline__ void mma16816(float* c, const uint32_t* a,
                                         uint32_t b0, uint32_t b1) {
    asm volatile(
        "mma.sync.aligned.m16n8k16.row.col.f32.f16.f16.f32 "
        "{%0,%1,%2,%3}, {%4,%5,%6,%7}, {%8,%9}, {%0,%1,%2,%3};"
        : "+f"(c[0]), "+f"(c[1]), "+f"(c[2]), "+f"(c[3])
        : "r"(a[0]), "r"(a[1]), "r"(a[2]), "r"(a[3]), "r"(b0), "r"(b1));
}

// ---------------------------------------------------------------------------
// Pooling (float4) + self dtype-detect + out init. fp16 hi/lo outputs for A.
// One block (80 threads) per batch row; tx<75 owns one float4 of dims.
// lengths in [1,127]: raw word[1]==0 <=> int64 layout.
// ---------------------------------------------------------------------------
__global__ void __launch_bounds__(80) pool_kernel(
    const void* __restrict__ xv, const void* __restrict__ lenv,
    const float* __restrict__ emb, const float* __restrict__ b2,
    float* __restrict__ out)
{
    __shared__ int idx_s[MAX_LEN];
    const int b = blockIdx.x;
    const int tid = threadIdx.x;

    const int is64 = (((const unsigned*)lenv)[1] == 0u);

    int len;
    if (is64) {
        len = (int)((const long long*)lenv)[b];
        for (int i = tid; i < len; i += 80)
            idx_s[i] = (int)((const long long*)xv)[(long)b * MAX_LEN + i];
    } else {
        len = ((const int*)lenv)[b];
        for (int i = tid; i < len; i += 80)
            idx_s[i] = ((const int*)xv)[(long)b * MAX_LEN + i];
    }
    __syncthreads();

    const long rowb = (long)b * KPAD;

    // out init: out[b][c] = b2[c]; mma accumulates atomically afterwards
    if (tid < NCLS)
        out[(long)b * NCLS + tid] = __ldg(&b2[tid]);

    if (tid >= 75) {
        // zero K padding cols 600..639 (5 threads x 8 halves)
        const int d0 = REP_D + (tid - 75) * 8;
        *(uint4*)&g_a_hi[rowb + d0] = make_uint4(0u, 0u, 0u, 0u);
        *(uint4*)&g_a_lo[rowb + d0] = make_uint4(0u, 0u, 0u, 0u);
        return;
    }

    const float4* base = (const float4*)emb;   // emb rows: 75 float4 each
    float4 s  = make_float4(0.f, 0.f, 0.f, 0.f);
    float4 mx = make_float4(-3.402823466e38f, -3.402823466e38f,
                            -3.402823466e38f, -3.402823466e38f);
#pragma unroll 4
    for (int t = 0; t < len; ++t) {
        const float4 v = __ldg(&base[(long)idx_s[t] * 75 + tid]);
        s.x += v.x; s.y += v.y; s.z += v.z; s.w += v.w;
        mx.x = fmaxf(mx.x, v.x); mx.y = fmaxf(mx.y, v.y);
        mx.z = fmaxf(mx.z, v.z); mx.w = fmaxf(mx.w, v.w);
    }
    const float inv = 1.0f / (float)len;
    const float a0 = s.x * inv, a1 = s.y * inv, a2 = s.z * inv, a3 = s.w * inv;

    const int d = 4 * tid;
    {
        const __half h0 = __float2half_rn(a0), h1 = __float2half_rn(a1);
        const __half h2 = __float2half_rn(a2), h3 = __float2half_rn(a3);
        __half2 p0(h0, h1), p1(h2, h3);
        *(uint2*)&g_a_hi[rowb + d] = make_uint2(*(uint32_t*)&p0, *(uint32_t*)&p1);
        __half2 q0(__float2half_rn(a0 - __half2float(h0)),
                   __float2half_rn(a1 - __half2float(h1)));
        __half2 q1(__float2half_rn(a2 - __half2float(h2)),
                   __float2half_rn(a3 - __half2float(h3)));
        *(uint2*)&g_a_lo[rowb + d] = make_uint2(*(uint32_t*)&q0, *(uint32_t*)&q1);
    }
    {
        const __half h0 = __float2half_rn(mx.x), h1 = __float2half_rn(mx.y);
        const __half h2 = __float2half_rn(mx.z), h3 = __float2half_rn(mx.w);
        __half2 p0(h0, h1), p1(h2, h3);
        *(uint2*)&g_a_hi[rowb + EMB_D + d] = make_uint2(*(uint32_t*)&p0, *(uint32_t*)&p1);
        __half2 q0(__float2half_rn(mx.x - __half2float(h0)),
                   __float2half_rn(mx.y - __half2float(h1)));
        __half2 q1(__float2half_rn(mx.z - __half2float(h2)),
                   __float2half_rn(mx.w - __half2float(h3)));
        *(uint2*)&g_a_lo[rowb + EMB_D + d] = make_uint2(*(uint32_t*)&q0, *(uint32_t*)&q1);
    }
}

// ---------------------------------------------------------------------------
// W1 [600,1000] fp32 -> transposed padded fp16 [1024,640]
// smem 32x32 tile transpose: coalesced reads AND writes.
// ---------------------------------------------------------------------------
__global__ void __launch_bounds__(256) convert_w1_kernel(const float* __restrict__ W1) {
    __shared__ float tile[32][33];
    const int k0 = blockIdx.x * 32;
    const int n0 = blockIdx.y * 32;
    const int tx = threadIdx.x;   // 0..31
    const int ty = threadIdx.y;   // 0..7

#pragma unroll
    for (int i = 0; i < 4; ++i) {
        const int k = k0 + ty + i * 8;
        const int n = n0 + tx;
        tile[ty + i * 8][tx] = (k < REP_D && n < HID) ? __ldg(&W1[(long)k * HID + n]) : 0.0f;
    }
    __syncthreads();

#pragma unroll
    for (int i = 0; i < 4; ++i) {
        const int n = n0 + ty + i * 8;
        const int k = k0 + tx;
        g_b_hi[(long)n * KPAD + k] = __float2half_rn(tile[tx][ty + i * 8]);
    }
}

// ---------------------------------------------------------------------------
// Fused GEMM1 (fp16 2-term emulated fp32 via mma.sync) + bias + ReLU + GEMM2.
// CTA tile M=128,N=128; 8 warps (2m x 4n), warp tile 64x32.
// BK=32, 20 chunks, double-buffered stages of 3 tiles [A_HI, A_LO, B_HI].
// acc += Ahi*Bh + Alo*Bh   (= A*Bh exactly to 2^-22; dropped A*Blo ~ 2^-11)
// ---------------------------------------------------------------------------
#define LDSH 40                       // halves per smem row (32 + 8 pad)
#define TILE_B (128 * LDSH * 2)       // 10240
#define STAGE_B (3 * TILE_B)          // 30720: [A_HI, A_LO, B_HI]
#define SMEM_BYTES (2 * STAGE_B)      // 61440

__device__ __forceinline__ void fill_stage(
    uint32_t sbase, int tid, int kc,
    const __half* gah, const __half* gal, const __half* gbh)
{
#pragma unroll
    for (int i = 0; i < 2; ++i) {
        const int e = tid + i * 256;
        const int row = e >> 2, seg = e & 3;
        const uint32_t so = (uint32_t)(row * LDSH + seg * 8) * 2;
        const long go = (long)row * KPAD + kc + seg * 8;
        cp_async16(sbase + 0 * TILE_B + so, gah + go);
        cp_async16(sbase + 1 * TILE_B + so, gal + go);
        cp_async16(sbase + 2 * TILE_B + so, gbh + go);
    }
}

__global__ void __launch_bounds__(256, 2) mma_kernel(
    const float* __restrict__ b1, const float* __restrict__ W2,
    float* __restrict__ out)
{
    extern __shared__ __align__(128) char smem[];
    const uint32_t sb = smem_u32(smem);
    const int tid  = threadIdx.x;
    const int wid  = tid >> 5;
    const int lane = tid & 31;
    const int warp_m = wid >> 2;      // 0..1
    const int warp_n = wid & 3;       // 0..3
    const int n0 = blockIdx.x * 128;
    const int m0 = blockIdx.y * 128;

    const __half* gah = g_a_hi + (long)m0 * KPAD;
    const __half* gal = g_a_lo + (long)m0 * KPAD;
    const __half* gbh = g_b_hi + (long)n0 * KPAD;

    float acc[4][4][4];
#pragma unroll
    for (int a = 0; a < 4; ++a)
#pragma unroll
        for (int b = 0; b < 4; ++b)
#pragma unroll
            for (int d = 0; d < 4; ++d) acc[a][b][d] = 0.0f;

    // ldmatrix per-lane address components (in halves)
    const int a_row16 = (lane & 7) + ((lane >> 3) & 1) * 8;
    const int a_koff  = (lane >> 4) * 8;
    const int b_n16   = (lane & 7) + (lane >> 4) * 8;
    const int b_koff  = ((lane >> 3) & 1) * 8;

    fill_stage(sb, tid, 0, gah, gal, gbh);
    CP_COMMIT();

    for (int c = 0; c < NCHUNK; ++c) {
        const uint32_t cur = sb + (uint32_t)(c & 1) * STAGE_B;

        if (c + 1 < NCHUNK) {
            fill_stage(sb + (uint32_t)((c + 1) & 1) * STAGE_B, tid,
                       (c + 1) * BK, gah, gal, gbh);
            CP_COMMIT();
            CP_WAIT(1);
        } else {
            CP_WAIT(0);
        }
        __syncthreads();

#pragma unroll
        for (int ks = 0; ks < BK / 16; ++ks) {
            const int k0 = ks * 16;
            uint32_t bh[4][2];
            uint32_t af[4][4];

            // B fragments (reused across both passes)
#pragma unroll
            for (int nf2 = 0; nf2 < 2; ++nf2) {
                const uint32_t boff =
                    (uint32_t)((warp_n * 32 + nf2 * 16 + b_n16) * LDSH + k0 + b_koff) * 2;
                uint32_t r[4];
                ldsm4(r, cur + 2 * TILE_B + boff);
                bh[nf2 * 2 + 0][0] = r[0]; bh[nf2 * 2 + 0][1] = r[1];
                bh[nf2 * 2 + 1][0] = r[2]; bh[nf2 * 2 + 1][1] = r[3];
            }

            // pass 1: A_hi x B
#pragma unroll
            for (int mf = 0; mf < 4; ++mf)
                ldsm4(af[mf], cur + 0 * TILE_B +
                      (uint32_t)((warp_m * 64 + mf * 16 + a_row16) * LDSH + k0 + a_koff) * 2);
#pragma unroll
            for (int mf = 0; mf < 4; ++mf)
#pragma unroll
                for (int nf = 0; nf < 4; ++nf)
                    mma16816(acc[mf][nf], af[mf], bh[nf][0], bh[nf][1]);

            // pass 2: A_lo x B (overwrite af)
#pragma unroll
            for (int mf = 0; mf < 4; ++mf)
                ldsm4(af[mf], cur + 1 * TILE_B +
                      (uint32_t)((warp_m * 64 + mf * 16 + a_row16) * LDSH + k0 + a_koff) * 2);
#pragma unroll
            for (int mf = 0; mf < 4; ++mf)
#pragma unroll
                for (int nf = 0; nf < 4; ++nf)
                    mma16816(acc[mf][nf], af[mf], bh[nf][0], bh[nf][1]);
        }
        __syncthreads();
    }

    // --- Fused epilogue: bias + relu + W2 dot + atomic accumulate ---
    float* w2s = (float*)(smem);            // 128*5 floats
    float* b1s = (float*)(smem + 2560);     // 128 floats
    for (int i = tid; i < 128 * NCLS; i += 256) {
        const int n = n0 + i / NCLS;
        w2s[i] = (n < HID) ? __ldg(&W2[(long)n * NCLS + (i % NCLS)]) : 0.0f;
    }
    if (tid < 128) {
        const int n = n0 + tid;
        b1s[tid] = (n < HID) ? __ldg(&b1[n]) : 0.0f;
    }
    __syncthreads();

#pragma unroll
    for (int mf = 0; mf < 4; ++mf) {
#pragma unroll
        for (int h = 0; h < 2; ++h) {
            const int m = m0 + warp_m * 64 + mf * 16 + (lane >> 2) + 8 * h;
            float p0 = 0.f, p1 = 0.f, p2 = 0.f, p3 = 0.f, p4 = 0.f;
#pragma unroll
            for (int nf = 0; nf < 4; ++nf) {
                const int nl = warp_n * 32 + nf * 8 + 2 * (lane & 3);
                const float v0 = fmaxf(acc[mf][nf][2 * h + 0] + b1s[nl], 0.0f);
                const float v1 = fmaxf(acc[mf][nf][2 * h + 1] + b1s[nl + 1], 0.0f);
                p0 += v0 * w2s[nl * NCLS + 0] + v1 * w2s[(nl + 1) * NCLS + 0];
                p1 += v0 * w2s[nl * NCLS + 1] + v1 * w2s[(nl + 1) * NCLS + 1];
                p2 += v0 * w2s[nl * NCLS + 2] + v1 * w2s[(nl + 1) * NCLS + 2];
                p3 += v0 * w2s[nl * NCLS + 3] + v1 * w2s[(nl + 1) * NCLS + 3];
                p4 += v0 * w2s[nl * NCLS + 4] + v1 * w2s[(nl + 1) * NCLS + 4];
            }
#pragma unroll
            for (int off = 1; off <= 2; off <<= 1) {
                p0 += __shfl_xor_sync(0xffffffffu, p0, off);
                p1 += __shfl_xor_sync(0xffffffffu, p1, off);
                p2 += __shfl_xor_sync(0xffffffffu, p2, off);
                p3 += __shfl_xor_sync(0xffffffffu, p3, off);
                p4 += __shfl_xor_sync(0xffffffffu, p4, off);
            }
            if ((lane & 3) == 0) {
                atomicAdd(&out[(long)m * NCLS + 0], p0);
                atomicAdd(&out[(long)m * NCLS + 1], p1);
                atomicAdd(&out[(long)m * NCLS + 2], p2);
                atomicAdd(&out[(long)m * NCLS + 3], p3);
                atomicAdd(&out[(long)m * NCLS + 4], p4);
            }
        }
    }
}

// ---------------------------------------------------------------------------
extern "C" void kernel_launch(void* const* d_in, const int* in_sizes, int n_in,
                              void* d_out, int out_size)
{
    const void*  x       = d_in[0];
    const void*  lengths = d_in[1];
    const float* emb     = (const float*)d_in[2];
    const float* W1      = (const float*)d_in[3];
    const float* b1      = (const float*)d_in[4];
    const float* W2      = (const float*)d_in[5];
    const float* b2      = (const float*)d_in[6];
    float* out = (float*)d_out;

    cudaFuncSetAttribute(mma_kernel, cudaFuncAttributeMaxDynamicSharedMemorySize,
                         (int)SMEM_BYTES);

    pool_kernel<<<B_SZ, 80>>>(x, lengths, emb, b2, out);

    dim3 cb(32, 8);
    dim3 cg(KPAD / 32, NPAD / 32);   // (20, 32)
    convert_w1_kernel<<<cg, cb>>>(W1);

    dim3 g(NPAD / 128, B_SZ / 128);  // (8, 32)
    mma_kernel<<<g, 256, SMEM_BYTES>>>(b1, W2, out);
}

// round 8
// speedup vs baseline: 3.0057x; 1.2576x over previous
#include <cuda_runtime.h>
#include <cuda_fp16.h>
#include <cstdint>

// Problem constants
#define B_SZ 4096
#define MAX_LEN 128
#define EMB_D 300
#define REP_D 600
#define HID 1000
#define NCLS 5

#define KPAD 640      // 600 padded to 20 chunks of 32
#define NPAD 1024     // 1000 padded to 8 tiles of 128
#define BK 32
#define NCHUNK (KPAD / BK)       // 20
#define CONV_BLKS ((KPAD / 32) * (NPAD / 32))   // 20*32 = 640

// ---------------------------------------------------------------------------
// Scratch (no cudaMalloc allowed)
// ---------------------------------------------------------------------------
__device__ __align__(128) __half g_a[B_SZ * KPAD];   // rep fp16 [4096,640]
__device__ __align__(128) __half g_b[NPAD * KPAD];   // W1^T fp16 [1024,640]

// ---------------------------------------------------------------------------
// PTX helpers (family-portable: ldmatrix / mma.sync / cp.async)
// ---------------------------------------------------------------------------
__device__ __forceinline__ uint32_t smem_u32(const void* p) {
    uint32_t a;
    asm("{ .reg .u64 t; cvta.to.shared.u64 t, %1; cvt.u32.u64 %0, t; }"
        : "=r"(a) : "l"(p));
    return a;
}

__device__ __forceinline__ void cp_async16(uint32_t smem_dst, const void* gmem_src) {
    asm volatile("cp.async.ca.shared.global [%0], [%1], 16;"
                 :: "r"(smem_dst), "l"(gmem_src));
}
#define CP_COMMIT() asm volatile("cp.async.commit_group;" ::: "memory")
#define CP_WAIT(n)  asm volatile("cp.async.wait_group %0;" :: "n"(n) : "memory")

__device__ __forceinline__ void ldsm4(uint32_t* r, uint32_t addr) {
    asm volatile("ldmatrix.sync.aligned.m8n8.x4.shared.b16 {%0,%1,%2,%3}, [%4];"
                 : "=r"(r[0]), "=r"(r[1]), "=r"(r[2]), "=r"(r[3]) : "r"(addr));
}

__device__ __forceinline__ void mma16816(float* c, const uint32_t* a,
                                         uint32_t b0, uint32_t b1) {
    asm volatile(
        "mma.sync.aligned.m16n8k16.row.col.f32.f16.f16.f32 "
        "{%0,%1,%2,%3}, {%4,%5,%6,%7}, {%8,%9}, {%0,%1,%2,%3};"
        : "+f"(c[0]), "+f"(c[1]), "+f"(c[2]), "+f"(c[3])
        : "r"(a[0]), "r"(a[1]), "r"(a[2]), "r"(a[3]), "r"(b0), "r"(b1));
}

// ---------------------------------------------------------------------------
// Hybrid kernel: blocks [0, B_SZ) pool one batch row each; blocks
// [B_SZ, B_SZ+CONV_BLKS) transpose-convert one 32x32 tile of W1 to fp16.
// Pool: 80 threads, tx<75 owns one float4 of dims; emits fp16 rep + out init.
// lengths in [1,127]: raw word[1]==0 <=> int64 layout.
// ---------------------------------------------------------------------------
__global__ void __launch_bounds__(80) pool_conv_kernel(
    const void* __restrict__ xv, const void* __restrict__ lenv,
    const float* __restrict__ emb, const float* __restrict__ b2,
    const float* __restrict__ W1, float* __restrict__ out)
{
    __shared__ __align__(16) char sm[32 * 33 * 4];
    const int tid = threadIdx.x;

    if (blockIdx.x >= B_SZ) {
        // ---- W1 convert: 32x32 tile transpose, fp32 -> fp16 ----
        float* tile = (float*)sm;               // [32][33]
        const int cb = blockIdx.x - B_SZ;
        const int kb = (cb % (KPAD / 32)) * 32;
        const int nb = (cb / (KPAD / 32)) * 32;
        for (int i = tid; i < 1024; i += 80) {
            const int kk = i >> 5, nn = i & 31;
            const int k = kb + kk, n = nb + nn;
            tile[kk * 33 + nn] =
                (k < REP_D && n < HID) ? __ldg(&W1[(long)k * HID + n]) : 0.0f;
        }
        __syncthreads();
        for (int i = tid; i < 1024; i += 80) {
            const int nn = i >> 5, kk = i & 31;
            g_b[(long)(nb + nn) * KPAD + kb + kk] =
                __float2half_rn(tile[kk * 33 + nn]);
        }
        return;
    }

    // ---- pooling ----
    int* idx_s = (int*)sm;
    const int b = blockIdx.x;
    const int is64 = (((const unsigned*)lenv)[1] == 0u);

    int len;
    if (is64) {
        len = (int)((const long long*)lenv)[b];
        for (int i = tid; i < len; i += 80)
            idx_s[i] = (int)((const long long*)xv)[(long)b * MAX_LEN + i];
    } else {
        len = ((const int*)lenv)[b];
        for (int i = tid; i < len; i += 80)
            idx_s[i] = ((const int*)xv)[(long)b * MAX_LEN + i];
    }
    __syncthreads();

    const long rowb = (long)b * KPAD;

    // out init: out[b][c] = b2[c]; mma accumulates atomically afterwards
    if (tid < NCLS)
        out[(long)b * NCLS + tid] = __ldg(&b2[tid]);

    if (tid >= 75) {
        // zero K padding cols 600..639 (5 threads x 8 halves)
        const int d0 = REP_D + (tid - 75) * 8;
        *(uint4*)&g_a[rowb + d0] = make_uint4(0u, 0u, 0u, 0u);
        return;
    }

    const float4* base = (const float4*)emb;   // emb rows: 75 float4 each
    float4 s  = make_float4(0.f, 0.f, 0.f, 0.f);
    float4 mx = make_float4(-3.402823466e38f, -3.402823466e38f,
                            -3.402823466e38f, -3.402823466e38f);
#pragma unroll 4
    for (int t = 0; t < len; ++t) {
        const float4 v = __ldg(&base[(long)idx_s[t] * 75 + tid]);
        s.x += v.x; s.y += v.y; s.z += v.z; s.w += v.w;
        mx.x = fmaxf(mx.x, v.x); mx.y = fmaxf(mx.y, v.y);
        mx.z = fmaxf(mx.z, v.z); mx.w = fmaxf(mx.w, v.w);
    }
    const float inv = 1.0f / (float)len;

    const int d = 4 * tid;
    {
        __half2 p0(__float2half_rn(s.x * inv), __float2half_rn(s.y * inv));
        __half2 p1(__float2half_rn(s.z * inv), __float2half_rn(s.w * inv));
        *(uint2*)&g_a[rowb + d] = make_uint2(*(uint32_t*)&p0, *(uint32_t*)&p1);
    }
    {
        __half2 p0(__float2half_rn(mx.x), __float2half_rn(mx.y));
        __half2 p1(__float2half_rn(mx.z), __float2half_rn(mx.w));
        *(uint2*)&g_a[rowb + EMB_D + d] = make_uint2(*(uint32_t*)&p0, *(uint32_t*)&p1);
    }
}

// ---------------------------------------------------------------------------
// Fused GEMM1 (fp16 via mma.sync) + bias + ReLU + GEMM2.
// CTA tile M=128,N=128; 8 warps (2m x 4n), warp tile 64x32.
// BK=32, 20 chunks, double-buffered stages of 2 tiles [A, B].
// ---------------------------------------------------------------------------
#define LDSH 40                       // halves per smem row (32 + 8 pad)
#define TILE_B (128 * LDSH * 2)       // 10240
#define STAGE_B (2 * TILE_B)          // 20480: [A, B]
#define SMEM_BYTES (2 * STAGE_B)      // 40960

__device__ __forceinline__ void fill_stage(
    uint32_t sbase, int tid, int kc,
    const __half* ga, const __half* gb)
{
#pragma unroll
    for (int i = 0; i < 2; ++i) {
        const int e = tid + i * 256;
        const int row = e >> 2, seg = e & 3;
        const uint32_t so = (uint32_t)(row * LDSH + seg * 8) * 2;
        const long go = (long)row * KPAD + kc + seg * 8;
        cp_async16(sbase + 0 * TILE_B + so, ga + go);
        cp_async16(sbase + 1 * TILE_B + so, gb + go);
    }
}

__global__ void __launch_bounds__(256, 2) mma_kernel(
    const float* __restrict__ b1, const float* __restrict__ W2,
    float* __restrict__ out)
{
    extern __shared__ __align__(128) char smem[];
    const uint32_t sb = smem_u32(smem);
    const int tid  = threadIdx.x;
    const int wid  = tid >> 5;
    const int lane = tid & 31;
    const int warp_m = wid >> 2;      // 0..1
    const int warp_n = wid & 3;       // 0..3
    const int n0 = blockIdx.x * 128;
    const int m0 = blockIdx.y * 128;

    const __half* ga = g_a + (long)m0 * KPAD;
    const __half* gb = g_b + (long)n0 * KPAD;

    float acc[4][4][4];
#pragma unroll
    for (int a = 0; a < 4; ++a)
#pragma unroll
        for (int b = 0; b < 4; ++b)
#pragma unroll
            for (int d = 0; d < 4; ++d) acc[a][b][d] = 0.0f;

    // ldmatrix per-lane address components (in halves)
    const int a_row16 = (lane & 7) + ((lane >> 3) & 1) * 8;
    const int a_koff  = (lane >> 4) * 8;
    const int b_n16   = (lane & 7) + (lane >> 4) * 8;
    const int b_koff  = ((lane >> 3) & 1) * 8;

    fill_stage(sb, tid, 0, ga, gb);
    CP_COMMIT();

    for (int c = 0; c < NCHUNK; ++c) {
        const uint32_t cur = sb + (uint32_t)(c & 1) * STAGE_B;

        if (c + 1 < NCHUNK) {
            fill_stage(sb + (uint32_t)((c + 1) & 1) * STAGE_B, tid,
                       (c + 1) * BK, ga, gb);
            CP_COMMIT();
            CP_WAIT(1);
        } else {
            CP_WAIT(0);
        }
        __syncthreads();

#pragma unroll
        for (int ks = 0; ks < BK / 16; ++ks) {
            const int k0 = ks * 16;
            uint32_t bh[4][2];
            uint32_t af[4][4];

#pragma unroll
            for (int nf2 = 0; nf2 < 2; ++nf2) {
                const uint32_t boff =
                    (uint32_t)((warp_n * 32 + nf2 * 16 + b_n16) * LDSH + k0 + b_koff) * 2;
                uint32_t r[4];
                ldsm4(r, cur + 1 * TILE_B + boff);
                bh[nf2 * 2 + 0][0] = r[0]; bh[nf2 * 2 + 0][1] = r[1];
                bh[nf2 * 2 + 1][0] = r[2]; bh[nf2 * 2 + 1][1] = r[3];
            }
#pragma unroll
            for (int mf = 0; mf < 4; ++mf)
                ldsm4(af[mf], cur + 0 * TILE_B +
                      (uint32_t)((warp_m * 64 + mf * 16 + a_row16) * LDSH + k0 + a_koff) * 2);
#pragma unroll
            for (int mf = 0; mf < 4; ++mf)
#pragma unroll
                for (int nf = 0; nf < 4; ++nf)
                    mma16816(acc[mf][nf], af[mf], bh[nf][0], bh[nf][1]);
        }
        __syncthreads();
    }

    // --- Fused epilogue: bias + relu + W2 dot + atomic accumulate ---
    float* w2s = (float*)(smem);            // 128*5 floats
    float* b1s = (float*)(smem + 2560);     // 128 floats
    for (int i = tid; i < 128 * NCLS; i += 256) {
        const int n = n0 + i / NCLS;
        w2s[i] = (n < HID) ? __ldg(&W2[(long)n * NCLS + (i % NCLS)]) : 0.0f;
    }
    if (tid < 128) {
        const int n = n0 + tid;
        b1s[tid] = (n < HID) ? __ldg(&b1[n]) : 0.0f;
    }
    __syncthreads();

#pragma unroll
    for (int mf = 0; mf < 4; ++mf) {
#pragma unroll
        for (int h = 0; h < 2; ++h) {
            const int m = m0 + warp_m * 64 + mf * 16 + (lane >> 2) + 8 * h;
            float p0 = 0.f, p1 = 0.f, p2 = 0.f, p3 = 0.f, p4 = 0.f;
#pragma unroll
            for (int nf = 0; nf < 4; ++nf) {
                const int nl = warp_n * 32 + nf * 8 + 2 * (lane & 3);
                const float v0 = fmaxf(acc[mf][nf][2 * h + 0] + b1s[nl], 0.0f);
                const float v1 = fmaxf(acc[mf][nf][2 * h + 1] + b1s[nl + 1], 0.0f);
                p0 += v0 * w2s[nl * NCLS + 0] + v1 * w2s[(nl + 1) * NCLS + 0];
                p1 += v0 * w2s[nl * NCLS + 1] + v1 * w2s[(nl + 1) * NCLS + 1];
                p2 += v0 * w2s[nl * NCLS + 2] + v1 * w2s[(nl + 1) * NCLS + 2];
                p3 += v0 * w2s[nl * NCLS + 3] + v1 * w2s[(nl + 1) * NCLS + 3];
                p4 += v0 * w2s[nl * NCLS + 4] + v1 * w2s[(nl + 1) * NCLS + 4];
            }
#pragma unroll
            for (int off = 1; off <= 2; off <<= 1) {
                p0 += __shfl_xor_sync(0xffffffffu, p0, off);
                p1 += __shfl_xor_sync(0xffffffffu, p1, off);
                p2 += __shfl_xor_sync(0xffffffffu, p2, off);
                p3 += __shfl_xor_sync(0xffffffffu, p3, off);
                p4 += __shfl_xor_sync(0xffffffffu, p4, off);
            }
            if ((lane & 3) == 0) {
                atomicAdd(&out[(long)m * NCLS + 0], p0);
                atomicAdd(&out[(long)m * NCLS + 1], p1);
                atomicAdd(&out[(long)m * NCLS + 2], p2);
                atomicAdd(&out[(long)m * NCLS + 3], p3);
                atomicAdd(&out[(long)m * NCLS + 4], p4);
            }
        }
    }
}

// ---------------------------------------------------------------------------
extern "C" void kernel_launch(void* const* d_in, const int* in_sizes, int n_in,
                              void* d_out, int out_size)
{
    const void*  x       = d_in[0];
    const void*  lengths = d_in[1];
    const float* emb     = (const float*)d_in[2];
    const float* W1      = (const float*)d_in[3];
    const float* b1      = (const float*)d_in[4];
    const float* W2      = (const float*)d_in[5];
    const float* b2      = (const float*)d_in[6];
    float* out = (float*)d_out;

    cudaFuncSetAttribute(mma_kernel, cudaFuncAttributeMaxDynamicSharedMemorySize,
                         (int)SMEM_BYTES);

    pool_conv_kernel<<<B_SZ + CONV_BLKS, 80>>>(x, lengths, emb, b2, W1, out);

    dim3 g(NPAD / 128, B_SZ / 128);  // (8, 32)
    mma_kernel<<<g, 256, SMEM_BYTES>>>(b1, W2, out);
}